// round 1
// baseline (speedup 1.0000x reference)
#include <cuda_runtime.h>
#include <math.h>

#define Bn  2
#define Tn  2048
#define Dn  1024
#define Hn  16
#define HDn 64
#define M_TOT (Bn*Tn)          // 4096
#define N_QKV (3*Dn)           // 3072
#define SD  68                 // smem row stride (floats) for attention tiles

// -------- scratch (device globals: allocation-free) --------
__device__ float g_q[(size_t)Bn*Hn*Tn*HDn];
__device__ float g_k[(size_t)Bn*Hn*Tn*HDn];
__device__ float g_v[(size_t)Bn*Hn*Tn*HDn];
__device__ float g_y[(size_t)M_TOT*Dn];
__device__ float g_z[(size_t)M_TOT*Dn];

// ============================================================
// Kernel 1: QKV GEMM  C = x[4096,1024] @ W_proj[1024,3072] + b
// scatter into g_q/g_k/g_v with [B,H,T,HD] layout
// ============================================================
__global__ __launch_bounds__(256) void qkv_gemm(
    const float* __restrict__ A, const float* __restrict__ Wp,
    const float* __restrict__ bp)
{
    const int K = Dn, N = N_QKV;
    __shared__ float As[8][128];
    __shared__ float Bs[8][128];

    int tid = threadIdx.x;
    int m0 = blockIdx.y * 128, n0 = blockIdx.x * 128;

    int ar  = tid >> 1;            // 0..127
    int ac4 = (tid & 1) * 4;       // 0 or 4
    int br  = tid >> 5;            // 0..7
    int bc4 = (tid & 31) * 4;      // 0..124

    const float* Aptr = A  + (size_t)(m0 + ar) * K + ac4;
    const float* Bptr = Wp + (size_t)br * N + n0 + bc4;

    int trow = tid >> 4, tcol = tid & 15;
    int tm = trow * 8,   tn = tcol * 8;

    float acc[8][8];
    #pragma unroll
    for (int i = 0; i < 8; i++)
        #pragma unroll
        for (int j = 0; j < 8; j++) acc[i][j] = 0.f;

    for (int k0 = 0; k0 < K; k0 += 8) {
        float4 av = *(const float4*)(Aptr + k0);
        float4 bv = *(const float4*)(Bptr + (size_t)k0 * N);
        As[ac4+0][ar] = av.x; As[ac4+1][ar] = av.y;
        As[ac4+2][ar] = av.z; As[ac4+3][ar] = av.w;
        *(float4*)&Bs[br][bc4] = bv;
        __syncthreads();

        #pragma unroll
        for (int kk = 0; kk < 8; kk++) {
            float a[8], b[8];
            *(float4*)(a)   = *(float4*)&As[kk][tm];
            *(float4*)(a+4) = *(float4*)&As[kk][tm+4];
            *(float4*)(b)   = *(float4*)&Bs[kk][tn];
            *(float4*)(b+4) = *(float4*)&Bs[kk][tn+4];
            #pragma unroll
            for (int i = 0; i < 8; i++)
                #pragma unroll
                for (int j = 0; j < 8; j++)
                    acc[i][j] += a[i] * b[j];
        }
        __syncthreads();
    }

    // epilogue: add bias, scatter to q/k/v in [B,H,T,HD]
    float bias[8];
    *(float4*)(bias)   = *(const float4*)(bp + n0 + tn);
    *(float4*)(bias+4) = *(const float4*)(bp + n0 + tn + 4);

    int n     = n0 + tn;               // multiple of 8 -> single (which,h) run
    int which = n >> 10;
    int rem   = n & 1023;
    int h     = rem >> 6;
    int d     = rem & 63;
    float* dstbase = (which == 0) ? g_q : (which == 1) ? g_k : g_v;

    #pragma unroll
    for (int i = 0; i < 8; i++) {
        int m = m0 + tm + i;
        int b = m >> 11;               // /2048
        int t = m & 2047;
        float* dst = dstbase + (((size_t)(b*Hn + h)*Tn + t)*HDn + d);
        float4 v0, v1;
        v0.x = acc[i][0]+bias[0]; v0.y = acc[i][1]+bias[1];
        v0.z = acc[i][2]+bias[2]; v0.w = acc[i][3]+bias[3];
        v1.x = acc[i][4]+bias[4]; v1.y = acc[i][5]+bias[5];
        v1.z = acc[i][6]+bias[6]; v1.w = acc[i][7]+bias[7];
        *(float4*)(dst)     = v0;
        *(float4*)(dst + 4) = v1;
    }
}

// ============================================================
// Kernel 2: causal attention, one CTA per (b, h, 64-row q tile)
// scores = (q.kT)/8, exp (no max-sub needed: |s|<~4, masked=0),
// wts = num / (rowsum + 1e-9), O = wts @ V  -> g_y [B,T,D]
// ============================================================
extern __shared__ float sm_attn[];

__global__ __launch_bounds__(256) void attn_kernel()
{
    float* Qt = sm_attn;                // [64][SD] d-major
    float* Kt = sm_attn + 64*SD;        // [64][SD] d-major
    float* Pt = sm_attn + 2*64*SD;      // [64][SD] j-major (P transposed)
    float* Vs = sm_attn + 3*64*SD;      // [64][SD] j-major

    int qb = blockIdx.x;   // 0..31
    int h  = blockIdx.y;
    int b  = blockIdx.z;
    int tid = threadIdx.x;

    size_t head_off = ((size_t)(b*Hn + h)) * Tn * HDn;
    const float* qg = g_q + head_off;
    const float* kg = g_k + head_off;
    const float* vg = g_v + head_off;

    int lr = tid >> 2;            // 0..63 (row loader)
    int lc = (tid & 3) * 16;      // 0,16,32,48

    // load Q tile transposed: Qt[d][i]
    {
        const float* src = qg + (size_t)(qb*64 + lr)*HDn + lc;
        #pragma unroll
        for (int q4 = 0; q4 < 4; q4++) {
            float4 v = *(const float4*)(src + q4*4);
            int d = lc + q4*4;
            Qt[(d+0)*SD + lr] = v.x; Qt[(d+1)*SD + lr] = v.y;
            Qt[(d+2)*SD + lr] = v.z; Qt[(d+3)*SD + lr] = v.w;
        }
    }

    int trow = tid >> 4, tcol = tid & 15;
    int i0 = trow * 4;     // query rows
    int j0 = tcol * 4;     // key cols (S) / out dims d0 (PV)

    float o[4][4];
    float dpart[4] = {0.f, 0.f, 0.f, 0.f};
    #pragma unroll
    for (int r = 0; r < 4; r++)
        #pragma unroll
        for (int c = 0; c < 4; c++) o[r][c] = 0.f;

    for (int kb = 0; kb <= qb; kb++) {
        __syncthreads();   // previous-iter readers done (also covers Qt load)

        // load K tile transposed + V tile natural
        {
            const float* ks = kg + (size_t)(kb*64 + lr)*HDn + lc;
            const float* vs = vg + (size_t)(kb*64 + lr)*HDn + lc;
            #pragma unroll
            for (int q4 = 0; q4 < 4; q4++) {
                float4 v = *(const float4*)(ks + q4*4);
                int d = lc + q4*4;
                Kt[(d+0)*SD + lr] = v.x; Kt[(d+1)*SD + lr] = v.y;
                Kt[(d+2)*SD + lr] = v.z; Kt[(d+3)*SD + lr] = v.w;
                *(float4*)&Vs[lr*SD + lc + q4*4] = *(const float4*)(vs + q4*4);
            }
        }
        __syncthreads();

        // S = Q @ K^T   (4x4 micro)
        float s[4][4];
        #pragma unroll
        for (int r = 0; r < 4; r++)
            #pragma unroll
            for (int c = 0; c < 4; c++) s[r][c] = 0.f;

        #pragma unroll 4
        for (int d = 0; d < 64; d++) {
            float4 q4 = *(float4*)&Qt[d*SD + i0];
            float4 k4 = *(float4*)&Kt[d*SD + j0];
            float qa[4] = {q4.x, q4.y, q4.z, q4.w};
            float ka[4] = {k4.x, k4.y, k4.z, k4.w};
            #pragma unroll
            for (int r = 0; r < 4; r++)
                #pragma unroll
                for (int c = 0; c < 4; c++)
                    s[r][c] += qa[r] * ka[c];
        }

        // exp + causal mask on the diagonal tile; write P transposed
        bool diag = (kb == qb);
        float p[4][4];
        #pragma unroll
        for (int r = 0; r < 4; r++) {
            #pragma unroll
            for (int c = 0; c < 4; c++) {
                float e;
                if (diag && (j0 + c > i0 + r)) e = 0.f;
                else e = __expf(s[r][c] * 0.125f);
                p[r][c] = e;
                dpart[r] += e;
            }
        }
        #pragma unroll
        for (int c = 0; c < 4; c++) {
            float4 pv;
            pv.x = p[0][c]; pv.y = p[1][c]; pv.z = p[2][c]; pv.w = p[3][c];
            *(float4*)&Pt[(j0 + c)*SD + i0] = pv;
        }
        __syncthreads();

        // O += P @ V  (reduce over keys j)
        #pragma unroll 4
        for (int j = 0; j < 64; j++) {
            float4 p4 = *(float4*)&Pt[j*SD + i0];
            float4 v4 = *(float4*)&Vs[j*SD + j0];   // j0 == d0 here
            float pa[4] = {p4.x, p4.y, p4.z, p4.w};
            float va[4] = {v4.x, v4.y, v4.z, v4.w};
            #pragma unroll
            for (int r = 0; r < 4; r++)
                #pragma unroll
                for (int c = 0; c < 4; c++)
                    o[r][c] += pa[r] * va[c];
        }
    }

    // reduce row sums across the 16 column-threads (xor within 16-lane half)
    #pragma unroll
    for (int off = 8; off; off >>= 1)
        #pragma unroll
        for (int r = 0; r < 4; r++)
            dpart[r] += __shfl_xor_sync(0xffffffffu, dpart[r], off);

    float inv[4];
    #pragma unroll
    for (int r = 0; r < 4; r++) inv[r] = 1.f / (dpart[r] + 1e-9f);

    // write to y in [B,T,D] layout, column block h*64 + d0
    int t0 = qb*64 + i0;
    float* ybase = g_y + ((size_t)b*Tn + t0)*Dn + h*64 + j0;
    #pragma unroll
    for (int r = 0; r < 4; r++) {
        float4 ov;
        ov.x = o[r][0]*inv[r]; ov.y = o[r][1]*inv[r];
        ov.z = o[r][2]*inv[r]; ov.w = o[r][3]*inv[r];
        *(float4*)(ybase + (size_t)r*Dn) = ov;
    }
}

// ============================================================
// Kernel 3: out projection + residual: z = x + y @ W_out + b_out
// ============================================================
__global__ __launch_bounds__(256) void outproj_gemm(
    const float* __restrict__ X, const float* __restrict__ Wo,
    const float* __restrict__ bo)
{
    const int K = Dn, N = Dn;
    __shared__ float As[8][128];
    __shared__ float Bs[8][128];

    int tid = threadIdx.x;
    int m0 = blockIdx.y * 128, n0 = blockIdx.x * 128;

    int ar  = tid >> 1;
    int ac4 = (tid & 1) * 4;
    int br  = tid >> 5;
    int bc4 = (tid & 31) * 4;

    const float* Aptr = g_y + (size_t)(m0 + ar) * K + ac4;
    const float* Bptr = Wo  + (size_t)br * N + n0 + bc4;

    int trow = tid >> 4, tcol = tid & 15;
    int tm = trow * 8,   tn = tcol * 8;

    float acc[8][8];
    #pragma unroll
    for (int i = 0; i < 8; i++)
        #pragma unroll
        for (int j = 0; j < 8; j++) acc[i][j] = 0.f;

    for (int k0 = 0; k0 < K; k0 += 8) {
        float4 av = *(const float4*)(Aptr + k0);
        float4 bv = *(const float4*)(Bptr + (size_t)k0 * N);
        As[ac4+0][ar] = av.x; As[ac4+1][ar] = av.y;
        As[ac4+2][ar] = av.z; As[ac4+3][ar] = av.w;
        *(float4*)&Bs[br][bc4] = bv;
        __syncthreads();

        #pragma unroll
        for (int kk = 0; kk < 8; kk++) {
            float a[8], bb[8];
            *(float4*)(a)    = *(float4*)&As[kk][tm];
            *(float4*)(a+4)  = *(float4*)&As[kk][tm+4];
            *(float4*)(bb)   = *(float4*)&Bs[kk][tn];
            *(float4*)(bb+4) = *(float4*)&Bs[kk][tn+4];
            #pragma unroll
            for (int i = 0; i < 8; i++)
                #pragma unroll
                for (int j = 0; j < 8; j++)
                    acc[i][j] += a[i] * bb[j];
        }
        __syncthreads();
    }

    float bias[8];
    *(float4*)(bias)   = *(const float4*)(bo + n0 + tn);
    *(float4*)(bias+4) = *(const float4*)(bo + n0 + tn + 4);

    #pragma unroll
    for (int i = 0; i < 8; i++) {
        int m = m0 + tm + i;
        const float* xr = X + (size_t)m * Dn + n0 + tn;
        float4 x0 = *(const float4*)(xr);
        float4 x1 = *(const float4*)(xr + 4);
        float* zr = g_z + (size_t)m * Dn + n0 + tn;
        float4 v0, v1;
        v0.x = acc[i][0]+bias[0]+x0.x; v0.y = acc[i][1]+bias[1]+x0.y;
        v0.z = acc[i][2]+bias[2]+x0.z; v0.w = acc[i][3]+bias[3]+x0.w;
        v1.x = acc[i][4]+bias[4]+x1.x; v1.y = acc[i][5]+bias[5]+x1.y;
        v1.z = acc[i][6]+bias[6]+x1.z; v1.w = acc[i][7]+bias[7]+x1.w;
        *(float4*)(zr)     = v0;
        *(float4*)(zr + 4) = v1;
    }
}

// ============================================================
// Kernel 4: LayerNorm over last dim (1024), one CTA per row
// ============================================================
__global__ __launch_bounds__(256) void ln_kernel(
    const float* __restrict__ gamma, const float* __restrict__ beta,
    float* __restrict__ out)
{
    int row = blockIdx.x;
    int tid = threadIdx.x;
    const float* z = g_z + (size_t)row * Dn + tid*4;
    float4 v = *(const float4*)z;
    float s  = v.x + v.y + v.z + v.w;
    float ss = v.x*v.x + v.y*v.y + v.z*v.z + v.w*v.w;

    #pragma unroll
    for (int off = 16; off; off >>= 1) {
        s  += __shfl_xor_sync(0xffffffffu, s,  off);
        ss += __shfl_xor_sync(0xffffffffu, ss, off);
    }

    __shared__ float rs[8], rss[8];
    __shared__ float smu, srstd;
    int wid = tid >> 5, lane = tid & 31;
    if (lane == 0) { rs[wid] = s; rss[wid] = ss; }
    __syncthreads();
    if (tid == 0) {
        float S = 0.f, SS = 0.f;
        #pragma unroll
        for (int w = 0; w < 8; w++) { S += rs[w]; SS += rss[w]; }
        float mu  = S * (1.f / Dn);
        float var = SS * (1.f / Dn) - mu * mu;
        smu = mu;
        srstd = rsqrtf(var + 1e-5f);
    }
    __syncthreads();
    float mu = smu, rstd = srstd;

    float4 g4 = *(const float4*)(gamma + tid*4);
    float4 b4 = *(const float4*)(beta  + tid*4);
    float4 o;
    o.x = (v.x - mu)*rstd*g4.x + b4.x;
    o.y = (v.y - mu)*rstd*g4.y + b4.y;
    o.z = (v.z - mu)*rstd*g4.z + b4.z;
    o.w = (v.w - mu)*rstd*g4.w + b4.w;
    *(float4*)(out + (size_t)row * Dn + tid*4) = o;
}

// ============================================================
extern "C" void kernel_launch(void* const* d_in, const int* in_sizes, int n_in,
                              void* d_out, int out_size)
{
    (void)in_sizes; (void)n_in; (void)out_size;
    const float* x    = (const float*)d_in[0];
    // d_in[1] = attn_mask: deterministic causal, not needed
    const float* Wp   = (const float*)d_in[2];
    const float* bp   = (const float*)d_in[3];
    const float* Wo   = (const float*)d_in[4];
    const float* bo   = (const float*)d_in[5];
    const float* gam  = (const float*)d_in[6];
    const float* bet  = (const float*)d_in[7];
    float* out = (float*)d_out;

    qkv_gemm<<<dim3(N_QKV/128, M_TOT/128), 256>>>(x, Wp, bp);

    size_t smem = (size_t)4 * 64 * SD * sizeof(float);  // 69632 B
    cudaFuncSetAttribute(attn_kernel,
                         cudaFuncAttributeMaxDynamicSharedMemorySize,
                         (int)smem);
    attn_kernel<<<dim3(Tn/64, Hn, Bn), 256, smem>>>();

    outproj_gemm<<<dim3(Dn/128, M_TOT/128), 256>>>(x, Wo, bo);

    ln_kernel<<<M_TOT, 256>>>(gam, bet, out);
}

// round 2
// speedup vs baseline: 1.5178x; 1.5178x over previous
#include <cuda_runtime.h>
#include <math.h>
#include <stdint.h>

#define Bn  2
#define Tn  2048
#define Dn  1024
#define Hn  16
#define HDn 64
#define M_TOT (Bn*Tn)          // 4096
#define N_QKV (3*Dn)           // 3072
#define SD  68                 // smem row stride (floats) for attention tiles
#define KSTR 136               // GEMM smem row stride: 136 % 32 == 8 -> conflict-free frag loads

// -------- scratch (device globals: allocation-free) --------
__device__ float g_q[(size_t)Bn*Hn*Tn*HDn];
__device__ float g_k[(size_t)Bn*Hn*Tn*HDn];
__device__ float g_v[(size_t)Bn*Hn*Tn*HDn];
__device__ float g_y[(size_t)M_TOT*Dn];
__device__ float g_z[(size_t)M_TOT*Dn];

__device__ __forceinline__ float cvt_tf32(float x) {
    float r;
    asm("cvt.rna.tf32.f32 %0, %1;" : "=f"(r) : "f"(x));
    return r;
}

__device__ __forceinline__ void mma_tf32(float d[4],
                                         uint32_t a0, uint32_t a1, uint32_t a2, uint32_t a3,
                                         uint32_t b0, uint32_t b1) {
    asm volatile(
        "mma.sync.aligned.m16n8k8.row.col.f32.tf32.tf32.f32 "
        "{%0,%1,%2,%3}, {%4,%5,%6,%7}, {%8,%9}, {%0,%1,%2,%3};\n"
        : "+f"(d[0]), "+f"(d[1]), "+f"(d[2]), "+f"(d[3])
        : "r"(a0), "r"(a1), "r"(a2), "r"(a3), "r"(b0), "r"(b1));
}

// ============================================================
// tf32 tensor-core GEMM body (CTA 128x128, BK=16, 8 warps 64x32)
// A row-major [M,K], Bmat row-major [K,N]. Accumulates acc[4][4][4].
// ============================================================
struct GemmCore {
    template <int KDIM, int NDIM>
    static __device__ __forceinline__ void run(
        const float* __restrict__ A, const float* __restrict__ Bmat,
        int m0, int n0, float* As, float* Bs, float acc[4][4][4])
    {
        const int tid  = threadIdx.x;
        const int lane = tid & 31;
        const int warp = tid >> 5;
        const int wr = warp >> 2, wc = warp & 3;   // 2 x 4 warp grid
        const int wm = wr * 64,  wn = wc * 32;
        const int g  = lane >> 2, tg = lane & 3;

        // staging maps
        const int am = tid >> 1;                // A row 0..127
        const int ak = (tid & 1) * 8;           // A k-offset 0 or 8
        const int bk = tid >> 5;                // B row 0..7 (plus +8 pass)
        const int bn = (tid & 31) * 4;          // B col (float4)

        const float* Ag = A + (size_t)(m0 + am) * KDIM + ak;
        const float* Bg = Bmat + (size_t)bk * NDIM + n0 + bn;

        float4 ra0, ra1, rb0, rb1;
        ra0 = *(const float4*)(Ag);
        ra1 = *(const float4*)(Ag + 4);
        rb0 = *(const float4*)(Bg);
        rb1 = *(const float4*)(Bg + (size_t)8 * NDIM);

        const int NIT = KDIM / 16;
        for (int kt = 0; kt < NIT; kt++) {
            // store staged tile (cvt to tf32 bit patterns)
            As[(ak+0)*KSTR + am] = cvt_tf32(ra0.x);
            As[(ak+1)*KSTR + am] = cvt_tf32(ra0.y);
            As[(ak+2)*KSTR + am] = cvt_tf32(ra0.z);
            As[(ak+3)*KSTR + am] = cvt_tf32(ra0.w);
            As[(ak+4)*KSTR + am] = cvt_tf32(ra1.x);
            As[(ak+5)*KSTR + am] = cvt_tf32(ra1.y);
            As[(ak+6)*KSTR + am] = cvt_tf32(ra1.z);
            As[(ak+7)*KSTR + am] = cvt_tf32(ra1.w);
            float4 c0, c1;
            c0.x = cvt_tf32(rb0.x); c0.y = cvt_tf32(rb0.y);
            c0.z = cvt_tf32(rb0.z); c0.w = cvt_tf32(rb0.w);
            c1.x = cvt_tf32(rb1.x); c1.y = cvt_tf32(rb1.y);
            c1.z = cvt_tf32(rb1.z); c1.w = cvt_tf32(rb1.w);
            *(float4*)&Bs[bk*KSTR + bn]     = c0;
            *(float4*)&Bs[(bk+8)*KSTR + bn] = c1;
            __syncthreads();

            if (kt + 1 < NIT) {
                const float* Agn = Ag + (kt+1)*16;
                ra0 = *(const float4*)(Agn);
                ra1 = *(const float4*)(Agn + 4);
                const float* Bgn = Bg + (size_t)(kt+1)*16 * NDIM;
                rb0 = *(const float4*)(Bgn);
                rb1 = *(const float4*)(Bgn + (size_t)8 * NDIM);
            }

            #pragma unroll
            for (int ks = 0; ks < 2; ks++) {
                const int kb = ks * 8;
                uint32_t af[4][4];
                #pragma unroll
                for (int mt = 0; mt < 4; mt++) {
                    const float* pa = &As[(kb+tg)*KSTR + wm + mt*16 + g];
                    af[mt][0] = __float_as_uint(pa[0]);
                    af[mt][1] = __float_as_uint(pa[8]);
                    af[mt][2] = __float_as_uint(pa[4*KSTR]);
                    af[mt][3] = __float_as_uint(pa[4*KSTR + 8]);
                }
                #pragma unroll
                for (int nt = 0; nt < 4; nt++) {
                    const float* pb = &Bs[(kb+tg)*KSTR + wn + nt*8 + g];
                    uint32_t b0 = __float_as_uint(pb[0]);
                    uint32_t b1 = __float_as_uint(pb[4*KSTR]);
                    #pragma unroll
                    for (int mt = 0; mt < 4; mt++)
                        mma_tf32(acc[mt][nt], af[mt][0], af[mt][1], af[mt][2], af[mt][3], b0, b1);
                }
            }
            __syncthreads();
        }
    }
};

// ============================================================
// Kernel 1: QKV GEMM (tf32 MMA) -> scatter to g_q/g_k/g_v [B,H,T,HD]
// ============================================================
__global__ __launch_bounds__(256, 2) void qkv_gemm_tc(
    const float* __restrict__ A, const float* __restrict__ Wp,
    const float* __restrict__ bp)
{
    __shared__ float As[16*KSTR];
    __shared__ float Bs[16*KSTR];
    const int m0 = blockIdx.y * 128, n0 = blockIdx.x * 128;

    float acc[4][4][4];
    #pragma unroll
    for (int i = 0; i < 4; i++)
        #pragma unroll
        for (int j = 0; j < 4; j++)
            #pragma unroll
            for (int k = 0; k < 4; k++) acc[i][j][k] = 0.f;

    GemmCore::run<Dn, N_QKV>(A, Wp, m0, n0, As, Bs, acc);

    const int tid = threadIdx.x, lane = tid & 31, warp = tid >> 5;
    const int wr = warp >> 2, wc = warp & 3;
    const int g = lane >> 2, tg = lane & 3;

    const int n_warp = n0 + wc*32;          // 32-block inside one 64-block
    const int which = n_warp >> 10;
    const int h     = (n_warp >> 6) & 15;
    float* dstbase = (which == 0) ? g_q : (which == 1) ? g_k : g_v;

    #pragma unroll
    for (int nt = 0; nt < 4; nt++) {
        const int n = n_warp + nt*8 + 2*tg;
        const int d = n & 63;
        float2 bias = *(const float2*)(bp + n);
        #pragma unroll
        for (int mt = 0; mt < 4; mt++) {
            #pragma unroll
            for (int half = 0; half < 2; half++) {
                const int m = m0 + wr*64 + mt*16 + g + half*8;
                const int b = m >> 11, t = m & 2047;
                float2 v;
                v.x = acc[mt][nt][half*2+0] + bias.x;
                v.y = acc[mt][nt][half*2+1] + bias.y;
                *(float2*)(dstbase + (((size_t)(b*Hn + h)*Tn + t)*HDn + d)) = v;
            }
        }
    }
}

// ============================================================
// Kernel 2: causal attention (fp32 SIMT, unchanged from R1)
// ============================================================
extern __shared__ float sm_attn[];

__global__ __launch_bounds__(256) void attn_kernel()
{
    float* Qt = sm_attn;
    float* Kt = sm_attn + 64*SD;
    float* Pt = sm_attn + 2*64*SD;
    float* Vs = sm_attn + 3*64*SD;

    int qb = blockIdx.x;
    int h  = blockIdx.y;
    int b  = blockIdx.z;
    int tid = threadIdx.x;

    size_t head_off = ((size_t)(b*Hn + h)) * Tn * HDn;
    const float* qg = g_q + head_off;
    const float* kg = g_k + head_off;
    const float* vg = g_v + head_off;

    int lr = tid >> 2;
    int lc = (tid & 3) * 16;

    {
        const float* src = qg + (size_t)(qb*64 + lr)*HDn + lc;
        #pragma unroll
        for (int q4 = 0; q4 < 4; q4++) {
            float4 v = *(const float4*)(src + q4*4);
            int d = lc + q4*4;
            Qt[(d+0)*SD + lr] = v.x; Qt[(d+1)*SD + lr] = v.y;
            Qt[(d+2)*SD + lr] = v.z; Qt[(d+3)*SD + lr] = v.w;
        }
    }

    int trow = tid >> 4, tcol = tid & 15;
    int i0 = trow * 4;
    int j0 = tcol * 4;

    float o[4][4];
    float dpart[4] = {0.f, 0.f, 0.f, 0.f};
    #pragma unroll
    for (int r = 0; r < 4; r++)
        #pragma unroll
        for (int c = 0; c < 4; c++) o[r][c] = 0.f;

    for (int kb = 0; kb <= qb; kb++) {
        __syncthreads();

        {
            const float* ks = kg + (size_t)(kb*64 + lr)*HDn + lc;
            const float* vs = vg + (size_t)(kb*64 + lr)*HDn + lc;
            #pragma unroll
            for (int q4 = 0; q4 < 4; q4++) {
                float4 v = *(const float4*)(ks + q4*4);
                int d = lc + q4*4;
                Kt[(d+0)*SD + lr] = v.x; Kt[(d+1)*SD + lr] = v.y;
                Kt[(d+2)*SD + lr] = v.z; Kt[(d+3)*SD + lr] = v.w;
                *(float4*)&Vs[lr*SD + lc + q4*4] = *(const float4*)(vs + q4*4);
            }
        }
        __syncthreads();

        float s[4][4];
        #pragma unroll
        for (int r = 0; r < 4; r++)
            #pragma unroll
            for (int c = 0; c < 4; c++) s[r][c] = 0.f;

        #pragma unroll 4
        for (int d = 0; d < 64; d++) {
            float4 q4 = *(float4*)&Qt[d*SD + i0];
            float4 k4 = *(float4*)&Kt[d*SD + j0];
            float qa[4] = {q4.x, q4.y, q4.z, q4.w};
            float ka[4] = {k4.x, k4.y, k4.z, k4.w};
            #pragma unroll
            for (int r = 0; r < 4; r++)
                #pragma unroll
                for (int c = 0; c < 4; c++)
                    s[r][c] += qa[r] * ka[c];
        }

        bool diag = (kb == qb);
        float p[4][4];
        #pragma unroll
        for (int r = 0; r < 4; r++) {
            #pragma unroll
            for (int c = 0; c < 4; c++) {
                float e;
                if (diag && (j0 + c > i0 + r)) e = 0.f;
                else e = __expf(s[r][c] * 0.125f);
                p[r][c] = e;
                dpart[r] += e;
            }
        }
        #pragma unroll
        for (int c = 0; c < 4; c++) {
            float4 pv;
            pv.x = p[0][c]; pv.y = p[1][c]; pv.z = p[2][c]; pv.w = p[3][c];
            *(float4*)&Pt[(j0 + c)*SD + i0] = pv;
        }
        __syncthreads();

        #pragma unroll 4
        for (int j = 0; j < 64; j++) {
            float4 p4 = *(float4*)&Pt[j*SD + i0];
            float4 v4 = *(float4*)&Vs[j*SD + j0];
            float pa[4] = {p4.x, p4.y, p4.z, p4.w};
            float va[4] = {v4.x, v4.y, v4.z, v4.w};
            #pragma unroll
            for (int r = 0; r < 4; r++)
                #pragma unroll
                for (int c = 0; c < 4; c++)
                    o[r][c] += pa[r] * va[c];
        }
    }

    #pragma unroll
    for (int off = 8; off; off >>= 1)
        #pragma unroll
        for (int r = 0; r < 4; r++)
            dpart[r] += __shfl_xor_sync(0xffffffffu, dpart[r], off);

    float inv[4];
    #pragma unroll
    for (int r = 0; r < 4; r++) inv[r] = 1.f / (dpart[r] + 1e-9f);

    int t0 = qb*64 + i0;
    float* ybase = g_y + ((size_t)b*Tn + t0)*Dn + h*64 + j0;
    #pragma unroll
    for (int r = 0; r < 4; r++) {
        float4 ov;
        ov.x = o[r][0]*inv[r]; ov.y = o[r][1]*inv[r];
        ov.z = o[r][2]*inv[r]; ov.w = o[r][3]*inv[r];
        *(float4*)(ybase + (size_t)r*Dn) = ov;
    }
}

// ============================================================
// Kernel 3: out projection (tf32 MMA) + residual -> g_z
// ============================================================
__global__ __launch_bounds__(256, 2) void outproj_gemm_tc(
    const float* __restrict__ X, const float* __restrict__ Wo,
    const float* __restrict__ bo)
{
    __shared__ float As[16*KSTR];
    __shared__ float Bs[16*KSTR];
    const int m0 = blockIdx.y * 128, n0 = blockIdx.x * 128;

    float acc[4][4][4];
    #pragma unroll
    for (int i = 0; i < 4; i++)
        #pragma unroll
        for (int j = 0; j < 4; j++)
            #pragma unroll
            for (int k = 0; k < 4; k++) acc[i][j][k] = 0.f;

    GemmCore::run<Dn, Dn>(g_y, Wo, m0, n0, As, Bs, acc);

    const int tid = threadIdx.x, lane = tid & 31, warp = tid >> 5;
    const int wr = warp >> 2, wc = warp & 3;
    const int g = lane >> 2, tg = lane & 3;

    #pragma unroll
    for (int nt = 0; nt < 4; nt++) {
        const int n = n0 + wc*32 + nt*8 + 2*tg;
        float2 bias = *(const float2*)(bo + n);
        #pragma unroll
        for (int mt = 0; mt < 4; mt++) {
            #pragma unroll
            for (int half = 0; half < 2; half++) {
                const int m = m0 + wr*64 + mt*16 + g + half*8;
                float2 xr = *(const float2*)(X + (size_t)m * Dn + n);
                float2 v;
                v.x = acc[mt][nt][half*2+0] + bias.x + xr.x;
                v.y = acc[mt][nt][half*2+1] + bias.y + xr.y;
                *(float2*)(g_z + (size_t)m * Dn + n) = v;
            }
        }
    }
}

// ============================================================
// Kernel 4: LayerNorm over last dim (1024), one CTA per row
// ============================================================
__global__ __launch_bounds__(256) void ln_kernel(
    const float* __restrict__ gamma, const float* __restrict__ beta,
    float* __restrict__ out)
{
    int row = blockIdx.x;
    int tid = threadIdx.x;
    const float* z = g_z + (size_t)row * Dn + tid*4;
    float4 v = *(const float4*)z;
    float s  = v.x + v.y + v.z + v.w;
    float ss = v.x*v.x + v.y*v.y + v.z*v.z + v.w*v.w;

    #pragma unroll
    for (int off = 16; off; off >>= 1) {
        s  += __shfl_xor_sync(0xffffffffu, s,  off);
        ss += __shfl_xor_sync(0xffffffffu, ss, off);
    }

    __shared__ float rs[8], rss[8];
    __shared__ float smu, srstd;
    int wid = tid >> 5, lane = tid & 31;
    if (lane == 0) { rs[wid] = s; rss[wid] = ss; }
    __syncthreads();
    if (tid == 0) {
        float S = 0.f, SS = 0.f;
        #pragma unroll
        for (int w = 0; w < 8; w++) { S += rs[w]; SS += rss[w]; }
        float mu  = S * (1.f / Dn);
        float var = SS * (1.f / Dn) - mu * mu;
        smu = mu;
        srstd = rsqrtf(var + 1e-5f);
    }
    __syncthreads();
    float mu = smu, rstd = srstd;

    float4 g4 = *(const float4*)(gamma + tid*4);
    float4 b4 = *(const float4*)(beta  + tid*4);
    float4 o;
    o.x = (v.x - mu)*rstd*g4.x + b4.x;
    o.y = (v.y - mu)*rstd*g4.y + b4.y;
    o.z = (v.z - mu)*rstd*g4.z + b4.z;
    o.w = (v.w - mu)*rstd*g4.w + b4.w;
    *(float4*)(out + (size_t)row * Dn + tid*4) = o;
}

// ============================================================
extern "C" void kernel_launch(void* const* d_in, const int* in_sizes, int n_in,
                              void* d_out, int out_size)
{
    (void)in_sizes; (void)n_in; (void)out_size;
    const float* x    = (const float*)d_in[0];
    // d_in[1] = attn_mask: deterministic causal, not needed
    const float* Wp   = (const float*)d_in[2];
    const float* bp   = (const float*)d_in[3];
    const float* Wo   = (const float*)d_in[4];
    const float* bo   = (const float*)d_in[5];
    const float* gam  = (const float*)d_in[6];
    const float* bet  = (const float*)d_in[7];
    float* out = (float*)d_out;

    qkv_gemm_tc<<<dim3(N_QKV/128, M_TOT/128), 256>>>(x, Wp, bp);

    size_t smem = (size_t)4 * 64 * SD * sizeof(float);  // 69632 B
    cudaFuncSetAttribute(attn_kernel,
                         cudaFuncAttributeMaxDynamicSharedMemorySize,
                         (int)smem);
    attn_kernel<<<dim3(Tn/64, Hn, Bn), 256, smem>>>();

    outproj_gemm_tc<<<dim3(Dn/128, M_TOT/128), 256>>>(x, Wo, bo);

    ln_kernel<<<M_TOT, 256>>>(gam, bet, out);
}

// round 3
// speedup vs baseline: 2.3853x; 1.5716x over previous
#include <cuda_runtime.h>
#include <math.h>
#include <stdint.h>

#define Bn  2
#define Tn  2048
#define Dn  1024
#define Hn  16
#define HDn 64
#define M_TOT (Bn*Tn)          // 4096
#define N_QKV (3*Dn)           // 3072
#define KSTR 136               // GEMM smem row stride (conflict-free frag loads)
#define ASTR 68                // attention smem stride: 68 % 32 == 4 -> 4g+tg bank-perm

// -------- scratch (device globals: allocation-free) --------
__device__ float g_q[(size_t)Bn*Hn*Tn*HDn];
__device__ float g_k[(size_t)Bn*Hn*Tn*HDn];
__device__ float g_v[(size_t)Bn*Hn*Tn*HDn];
__device__ float g_y[(size_t)M_TOT*Dn];
__device__ float g_z[(size_t)M_TOT*Dn];

__device__ __forceinline__ float cvt_tf32(float x) {
    float r;
    asm("cvt.rna.tf32.f32 %0, %1;" : "=f"(r) : "f"(x));
    return r;
}

__device__ __forceinline__ void mma_tf32(float d[4],
                                         uint32_t a0, uint32_t a1, uint32_t a2, uint32_t a3,
                                         uint32_t b0, uint32_t b1) {
    asm volatile(
        "mma.sync.aligned.m16n8k8.row.col.f32.tf32.tf32.f32 "
        "{%0,%1,%2,%3}, {%4,%5,%6,%7}, {%8,%9}, {%0,%1,%2,%3};\n"
        : "+f"(d[0]), "+f"(d[1]), "+f"(d[2]), "+f"(d[3])
        : "r"(a0), "r"(a1), "r"(a2), "r"(a3), "r"(b0), "r"(b1));
}

// ============================================================
// tf32 tensor-core GEMM body (CTA 128x128, BK=16, 8 warps 64x32)
// ============================================================
struct GemmCore {
    template <int KDIM, int NDIM>
    static __device__ __forceinline__ void run(
        const float* __restrict__ A, const float* __restrict__ Bmat,
        int m0, int n0, float* As, float* Bs, float acc[4][4][4])
    {
        const int tid  = threadIdx.x;
        const int lane = tid & 31;
        const int warp = tid >> 5;
        const int wr = warp >> 2, wc = warp & 3;
        const int wm = wr * 64,  wn = wc * 32;
        const int g  = lane >> 2, tg = lane & 3;

        const int am = tid >> 1;
        const int ak = (tid & 1) * 8;
        const int bk = tid >> 5;
        const int bn = (tid & 31) * 4;

        const float* Ag = A + (size_t)(m0 + am) * KDIM + ak;
        const float* Bg = Bmat + (size_t)bk * NDIM + n0 + bn;

        float4 ra0, ra1, rb0, rb1;
        ra0 = *(const float4*)(Ag);
        ra1 = *(const float4*)(Ag + 4);
        rb0 = *(const float4*)(Bg);
        rb1 = *(const float4*)(Bg + (size_t)8 * NDIM);

        const int NIT = KDIM / 16;
        for (int kt = 0; kt < NIT; kt++) {
            As[(ak+0)*KSTR + am] = cvt_tf32(ra0.x);
            As[(ak+1)*KSTR + am] = cvt_tf32(ra0.y);
            As[(ak+2)*KSTR + am] = cvt_tf32(ra0.z);
            As[(ak+3)*KSTR + am] = cvt_tf32(ra0.w);
            As[(ak+4)*KSTR + am] = cvt_tf32(ra1.x);
            As[(ak+5)*KSTR + am] = cvt_tf32(ra1.y);
            As[(ak+6)*KSTR + am] = cvt_tf32(ra1.z);
            As[(ak+7)*KSTR + am] = cvt_tf32(ra1.w);
            float4 c0, c1;
            c0.x = cvt_tf32(rb0.x); c0.y = cvt_tf32(rb0.y);
            c0.z = cvt_tf32(rb0.z); c0.w = cvt_tf32(rb0.w);
            c1.x = cvt_tf32(rb1.x); c1.y = cvt_tf32(rb1.y);
            c1.z = cvt_tf32(rb1.z); c1.w = cvt_tf32(rb1.w);
            *(float4*)&Bs[bk*KSTR + bn]     = c0;
            *(float4*)&Bs[(bk+8)*KSTR + bn] = c1;
            __syncthreads();

            if (kt + 1 < NIT) {
                const float* Agn = Ag + (kt+1)*16;
                ra0 = *(const float4*)(Agn);
                ra1 = *(const float4*)(Agn + 4);
                const float* Bgn = Bg + (size_t)(kt+1)*16 * NDIM;
                rb0 = *(const float4*)(Bgn);
                rb1 = *(const float4*)(Bgn + (size_t)8 * NDIM);
            }

            #pragma unroll
            for (int ks = 0; ks < 2; ks++) {
                const int kb = ks * 8;
                uint32_t af[4][4];
                #pragma unroll
                for (int mt = 0; mt < 4; mt++) {
                    const float* pa = &As[(kb+tg)*KSTR + wm + mt*16 + g];
                    af[mt][0] = __float_as_uint(pa[0]);
                    af[mt][1] = __float_as_uint(pa[8]);
                    af[mt][2] = __float_as_uint(pa[4*KSTR]);
                    af[mt][3] = __float_as_uint(pa[4*KSTR + 8]);
                }
                #pragma unroll
                for (int nt = 0; nt < 4; nt++) {
                    const float* pb = &Bs[(kb+tg)*KSTR + wn + nt*8 + g];
                    uint32_t b0 = __float_as_uint(pb[0]);
                    uint32_t b1 = __float_as_uint(pb[4*KSTR]);
                    #pragma unroll
                    for (int mt = 0; mt < 4; mt++)
                        mma_tf32(acc[mt][nt], af[mt][0], af[mt][1], af[mt][2], af[mt][3], b0, b1);
                }
            }
            __syncthreads();
        }
    }
};

// ============================================================
// Kernel 1: QKV GEMM (tf32 MMA) -> scatter to g_q/g_k/g_v
// ============================================================
__global__ __launch_bounds__(256, 2) void qkv_gemm_tc(
    const float* __restrict__ A, const float* __restrict__ Wp,
    const float* __restrict__ bp)
{
    __shared__ float As[16*KSTR];
    __shared__ float Bs[16*KSTR];
    const int m0 = blockIdx.y * 128, n0 = blockIdx.x * 128;

    float acc[4][4][4];
    #pragma unroll
    for (int i = 0; i < 4; i++)
        #pragma unroll
        for (int j = 0; j < 4; j++)
            #pragma unroll
            for (int k = 0; k < 4; k++) acc[i][j][k] = 0.f;

    GemmCore::run<Dn, N_QKV>(A, Wp, m0, n0, As, Bs, acc);

    const int tid = threadIdx.x, lane = tid & 31, warp = tid >> 5;
    const int wr = warp >> 2, wc = warp & 3;
    const int g = lane >> 2, tg = lane & 3;

    const int n_warp = n0 + wc*32;
    const int which = n_warp >> 10;
    const int h     = (n_warp >> 6) & 15;
    float* dstbase = (which == 0) ? g_q : (which == 1) ? g_k : g_v;

    #pragma unroll
    for (int nt = 0; nt < 4; nt++) {
        const int n = n_warp + nt*8 + 2*tg;
        const int d = n & 63;
        float2 bias = *(const float2*)(bp + n);
        #pragma unroll
        for (int mt = 0; mt < 4; mt++) {
            #pragma unroll
            for (int half = 0; half < 2; half++) {
                const int m = m0 + wr*64 + mt*16 + g + half*8;
                const int b = m >> 11, t = m & 2047;
                float2 v;
                v.x = acc[mt][nt][half*2+0] + bias.x;
                v.y = acc[mt][nt][half*2+1] + bias.y;
                *(float2*)(dstbase + (((size_t)(b*Hn + h)*Tn + t)*HDn + d)) = v;
            }
        }
    }
}

// ============================================================
// Kernel 2: causal attention, tf32 tensor-core version
// CTA = (qb, h, b). 8 warps = 4 row-bands(16) x 2 halves(32 cols).
// Non-normalized O accumulation; single normalization at end.
// ============================================================
extern __shared__ float sm_attn[];

__global__ __launch_bounds__(256) void attn_tc()
{
    float* Qs = sm_attn;             // [64][ASTR] i-major (pre-scaled by 1/8)
    float* Ks = Qs + 64*ASTR;        // [64][ASTR] j-major natural
    float* Vt = Ks + 64*ASTR;        // [64][ASTR] d-major (transposed)
    float* Ps = Vt + 64*ASTR;        // [64][ASTR] i-major
    __shared__ float dsum[64];

    const int qb = blockIdx.x, h = blockIdx.y, b = blockIdx.z;
    const int tid = threadIdx.x, lane = tid & 31, warp = tid >> 5;
    const int g = lane >> 2, tg = lane & 3;
    const int band = warp >> 1, half = warp & 1;
    const int i0w = band * 16;       // warp's query-row band
    const int jd0 = half * 32;       // warp's S-col block == PV d block

    size_t head_off = ((size_t)(b*Hn + h)) * Tn * HDn;
    const float* qg = g_q + head_off;
    const float* kg = g_k + head_off;
    const float* vg = g_v + head_off;

    const int lr = tid >> 2;
    const int lc = (tid & 3) * 16;

    // load Q tile (apply 1/sqrt(HD)=1/8 here; power of 2, lossless)
    {
        const float* src = qg + (size_t)(qb*64 + lr)*HDn + lc;
        #pragma unroll
        for (int q4 = 0; q4 < 4; q4++) {
            float4 v = *(const float4*)(src + q4*4);
            float* dst = &Qs[lr*ASTR + lc + q4*4];
            dst[0] = cvt_tf32(v.x * 0.125f);
            dst[1] = cvt_tf32(v.y * 0.125f);
            dst[2] = cvt_tf32(v.z * 0.125f);
            dst[3] = cvt_tf32(v.w * 0.125f);
        }
    }
    if (tid < 64) dsum[tid] = 0.f;

    float o[4][4];
    #pragma unroll
    for (int nt = 0; nt < 4; nt++)
        #pragma unroll
        for (int e = 0; e < 4; e++) o[nt][e] = 0.f;
    float rs0 = 0.f, rs1 = 0.f;

    for (int kb = 0; kb <= qb; kb++) {
        __syncthreads();   // smem tiles free (also covers Q load / dsum init)

        // load K natural + V transposed (both tf32-rounded)
        {
            const float* ks = kg + (size_t)(kb*64 + lr)*HDn + lc;
            const float* vs = vg + (size_t)(kb*64 + lr)*HDn + lc;
            #pragma unroll
            for (int q4 = 0; q4 < 4; q4++) {
                float4 kv = *(const float4*)(ks + q4*4);
                float* kd = &Ks[lr*ASTR + lc + q4*4];
                kd[0] = cvt_tf32(kv.x); kd[1] = cvt_tf32(kv.y);
                kd[2] = cvt_tf32(kv.z); kd[3] = cvt_tf32(kv.w);
                float4 vv = *(const float4*)(vs + q4*4);
                int d = lc + q4*4;
                Vt[(d+0)*ASTR + lr] = cvt_tf32(vv.x);
                Vt[(d+1)*ASTR + lr] = cvt_tf32(vv.y);
                Vt[(d+2)*ASTR + lr] = cvt_tf32(vv.z);
                Vt[(d+3)*ASTR + lr] = cvt_tf32(vv.w);
            }
        }
        __syncthreads();

        // ---- S = Q K^T (warp strip 16 x 32) ----
        float s[4][4];
        #pragma unroll
        for (int nt = 0; nt < 4; nt++)
            #pragma unroll
            for (int e = 0; e < 4; e++) s[nt][e] = 0.f;

        #pragma unroll
        for (int k0 = 0; k0 < 64; k0 += 8) {
            uint32_t a0 = __float_as_uint(Qs[(i0w+g  )*ASTR + k0+tg  ]);
            uint32_t a1 = __float_as_uint(Qs[(i0w+g+8)*ASTR + k0+tg  ]);
            uint32_t a2 = __float_as_uint(Qs[(i0w+g  )*ASTR + k0+tg+4]);
            uint32_t a3 = __float_as_uint(Qs[(i0w+g+8)*ASTR + k0+tg+4]);
            #pragma unroll
            for (int nt = 0; nt < 4; nt++) {
                const int j0 = jd0 + nt*8;
                uint32_t b0 = __float_as_uint(Ks[(j0+g)*ASTR + k0+tg  ]);
                uint32_t b1 = __float_as_uint(Ks[(j0+g)*ASTR + k0+tg+4]);
                mma_tf32(s[nt], a0, a1, a2, a3, b0, b1);
            }
        }

        // ---- exp + causal mask (diag tile only), rowsums, P -> smem ----
        const bool diag = (kb == qb);
        #pragma unroll
        for (int nt = 0; nt < 4; nt++) {
            const int c = jd0 + nt*8 + 2*tg;
            float p0, p1, p2, p3;
            if (diag) {
                const int r0 = i0w + g, r1 = r0 + 8;
                p0 = (c   <= r0) ? __expf(s[nt][0]) : 0.f;
                p1 = (c+1 <= r0) ? __expf(s[nt][1]) : 0.f;
                p2 = (c   <= r1) ? __expf(s[nt][2]) : 0.f;
                p3 = (c+1 <= r1) ? __expf(s[nt][3]) : 0.f;
            } else {
                p0 = __expf(s[nt][0]); p1 = __expf(s[nt][1]);
                p2 = __expf(s[nt][2]); p3 = __expf(s[nt][3]);
            }
            rs0 += p0 + p1;
            rs1 += p2 + p3;
            float2 w0, w1;
            w0.x = cvt_tf32(p0); w0.y = cvt_tf32(p1);
            w1.x = cvt_tf32(p2); w1.y = cvt_tf32(p3);
            *(float2*)&Ps[(i0w+g  )*ASTR + c] = w0;
            *(float2*)&Ps[(i0w+g+8)*ASTR + c] = w1;
        }
        __syncthreads();

        // ---- O += P V (warp: rows i0w band, d cols jd0..+31, k = 64) ----
        #pragma unroll
        for (int k0 = 0; k0 < 64; k0 += 8) {
            uint32_t a0 = __float_as_uint(Ps[(i0w+g  )*ASTR + k0+tg  ]);
            uint32_t a1 = __float_as_uint(Ps[(i0w+g+8)*ASTR + k0+tg  ]);
            uint32_t a2 = __float_as_uint(Ps[(i0w+g  )*ASTR + k0+tg+4]);
            uint32_t a3 = __float_as_uint(Ps[(i0w+g+8)*ASTR + k0+tg+4]);
            #pragma unroll
            for (int nt = 0; nt < 4; nt++) {
                const int dn = jd0 + nt*8;
                uint32_t b0 = __float_as_uint(Vt[(dn+g)*ASTR + k0+tg  ]);
                uint32_t b1 = __float_as_uint(Vt[(dn+g)*ASTR + k0+tg+4]);
                mma_tf32(o[nt], a0, a1, a2, a3, b0, b1);
            }
        }
    }

    // combine row sums: reduce over tg lanes, then across the 2 half-warps
    rs0 += __shfl_xor_sync(0xffffffffu, rs0, 1);
    rs0 += __shfl_xor_sync(0xffffffffu, rs0, 2);
    rs1 += __shfl_xor_sync(0xffffffffu, rs1, 1);
    rs1 += __shfl_xor_sync(0xffffffffu, rs1, 2);
    if (tg == 0) {
        atomicAdd(&dsum[i0w+g],   rs0);
        atomicAdd(&dsum[i0w+g+8], rs1);
    }
    __syncthreads();
    const float inv0 = 1.f / (dsum[i0w+g]   + 1e-9f);
    const float inv1 = 1.f / (dsum[i0w+g+8] + 1e-9f);

    float* ybase = g_y + ((size_t)b*Tn + qb*64)*Dn + h*64;
    #pragma unroll
    for (int nt = 0; nt < 4; nt++) {
        const int c = jd0 + nt*8 + 2*tg;
        float2 w0, w1;
        w0.x = o[nt][0]*inv0; w0.y = o[nt][1]*inv0;
        w1.x = o[nt][2]*inv1; w1.y = o[nt][3]*inv1;
        *(float2*)(ybase + (size_t)(i0w+g  )*Dn + c) = w0;
        *(float2*)(ybase + (size_t)(i0w+g+8)*Dn + c) = w1;
    }
}

// ============================================================
// Kernel 3: out projection (tf32 MMA) + residual -> g_z
// ============================================================
__global__ __launch_bounds__(256, 2) void outproj_gemm_tc(
    const float* __restrict__ X, const float* __restrict__ Wo,
    const float* __restrict__ bo)
{
    __shared__ float As[16*KSTR];
    __shared__ float Bs[16*KSTR];
    const int m0 = blockIdx.y * 128, n0 = blockIdx.x * 128;

    float acc[4][4][4];
    #pragma unroll
    for (int i = 0; i < 4; i++)
        #pragma unroll
        for (int j = 0; j < 4; j++)
            #pragma unroll
            for (int k = 0; k < 4; k++) acc[i][j][k] = 0.f;

    GemmCore::run<Dn, Dn>(g_y, Wo, m0, n0, As, Bs, acc);

    const int tid = threadIdx.x, lane = tid & 31, warp = tid >> 5;
    const int wr = warp >> 2, wc = warp & 3;
    const int g = lane >> 2, tg = lane & 3;

    #pragma unroll
    for (int nt = 0; nt < 4; nt++) {
        const int n = n0 + wc*32 + nt*8 + 2*tg;
        float2 bias = *(const float2*)(bo + n);
        #pragma unroll
        for (int mt = 0; mt < 4; mt++) {
            #pragma unroll
            for (int half = 0; half < 2; half++) {
                const int m = m0 + wr*64 + mt*16 + g + half*8;
                float2 xr = *(const float2*)(X + (size_t)m * Dn + n);
                float2 v;
                v.x = acc[mt][nt][half*2+0] + bias.x + xr.x;
                v.y = acc[mt][nt][half*2+1] + bias.y + xr.y;
                *(float2*)(g_z + (size_t)m * Dn + n) = v;
            }
        }
    }
}

// ============================================================
// Kernel 4: LayerNorm over last dim (1024), one CTA per row
// ============================================================
__global__ __launch_bounds__(256) void ln_kernel(
    const float* __restrict__ gamma, const float* __restrict__ beta,
    float* __restrict__ out)
{
    int row = blockIdx.x;
    int tid = threadIdx.x;
    const float* z = g_z + (size_t)row * Dn + tid*4;
    float4 v = *(const float4*)z;
    float s  = v.x + v.y + v.z + v.w;
    float ss = v.x*v.x + v.y*v.y + v.z*v.z + v.w*v.w;

    #pragma unroll
    for (int off = 16; off; off >>= 1) {
        s  += __shfl_xor_sync(0xffffffffu, s,  off);
        ss += __shfl_xor_sync(0xffffffffu, ss, off);
    }

    __shared__ float rs[8], rss[8];
    __shared__ float smu, srstd;
    int wid = tid >> 5, lane = tid & 31;
    if (lane == 0) { rs[wid] = s; rss[wid] = ss; }
    __syncthreads();
    if (tid == 0) {
        float S = 0.f, SS = 0.f;
        #pragma unroll
        for (int w = 0; w < 8; w++) { S += rs[w]; SS += rss[w]; }
        float mu  = S * (1.f / Dn);
        float var = SS * (1.f / Dn) - mu * mu;
        smu = mu;
        srstd = rsqrtf(var + 1e-5f);
    }
    __syncthreads();
    float mu = smu, rstd = srstd;

    float4 g4 = *(const float4*)(gamma + tid*4);
    float4 b4 = *(const float4*)(beta  + tid*4);
    float4 o;
    o.x = (v.x - mu)*rstd*g4.x + b4.x;
    o.y = (v.y - mu)*rstd*g4.y + b4.y;
    o.z = (v.z - mu)*rstd*g4.z + b4.z;
    o.w = (v.w - mu)*rstd*g4.w + b4.w;
    *(float4*)(out + (size_t)row * Dn + tid*4) = o;
}

// ============================================================
extern "C" void kernel_launch(void* const* d_in, const int* in_sizes, int n_in,
                              void* d_out, int out_size)
{
    (void)in_sizes; (void)n_in; (void)out_size;
    const float* x    = (const float*)d_in[0];
    // d_in[1] = attn_mask: deterministic causal, not needed
    const float* Wp   = (const float*)d_in[2];
    const float* bp   = (const float*)d_in[3];
    const float* Wo   = (const float*)d_in[4];
    const float* bo   = (const float*)d_in[5];
    const float* gam  = (const float*)d_in[6];
    const float* bet  = (const float*)d_in[7];
    float* out = (float*)d_out;

    qkv_gemm_tc<<<dim3(N_QKV/128, M_TOT/128), 256>>>(x, Wp, bp);

    size_t smem = (size_t)4 * 64 * ASTR * sizeof(float);  // 69632 B
    cudaFuncSetAttribute(attn_tc,
                         cudaFuncAttributeMaxDynamicSharedMemorySize,
                         (int)smem);
    attn_tc<<<dim3(Tn/64, Hn, Bn), 256, smem>>>();

    outproj_gemm_tc<<<dim3(Dn/128, M_TOT/128), 256>>>(x, Wo, bo);

    ln_kernel<<<M_TOT, 256>>>(gam, bet, out);
}

// round 4
// speedup vs baseline: 4.2908x; 1.7988x over previous
#include <cuda_runtime.h>
#include <cuda_bf16.h>
#include <math.h>
#include <stdint.h>

#define Bn  2
#define Tn  2048
#define Dn  1024
#define Hn  16
#define HDn 64
#define M_TOT 4096
#define N_QKV 3072
#define GW  136    // GEMM smem word stride (136 % 32 == 8 -> bank bijection)
#define AW  72     // attention smem word stride (72 % 32 == 8)

// -------- scratch (device globals: allocation-free) --------
__device__ __nv_bfloat16 g_q[(size_t)Bn*Hn*Tn*HDn];
__device__ __nv_bfloat16 g_k[(size_t)Bn*Hn*Tn*HDn];
__device__ __nv_bfloat16 g_v[(size_t)Bn*Hn*Tn*HDn];
__device__ __nv_bfloat16 g_y[(size_t)M_TOT*Dn];
__device__ float g_z[(size_t)M_TOT*Dn];

// pack two fp32 -> bf16x2 word, lo half = first arg
__device__ __forceinline__ uint32_t pack_bf16(float lo, float hi) {
    uint32_t r;
    asm("cvt.rn.bf16x2.f32 %0, %1, %2;" : "=r"(r) : "f"(hi), "f"(lo));
    return r;
}

__device__ __forceinline__ void mma_bf16(float d[4],
                                         uint32_t a0, uint32_t a1, uint32_t a2, uint32_t a3,
                                         uint32_t b0, uint32_t b1) {
    asm volatile(
        "mma.sync.aligned.m16n8k16.row.col.f32.bf16.bf16.f32 "
        "{%0,%1,%2,%3}, {%4,%5,%6,%7}, {%8,%9}, {%0,%1,%2,%3};\n"
        : "+f"(d[0]), "+f"(d[1]), "+f"(d[2]), "+f"(d[3])
        : "r"(a0), "r"(a1), "r"(a2), "r"(a3), "r"(b0), "r"(b1));
}

// ============================================================
// bf16 GEMM core (CTA 128x128, BK=16, 8 warps of 64x32)
// A row-major (fp32 or bf16), B row-major fp32 [K,N].
// smem: packed k-pair words; As[k2][m] (GW stride), Bs[k2][n].
// ============================================================
template <int KD, int ND, bool ABF>
__device__ __forceinline__ void gemm_core(
    const void* __restrict__ Av, const float* __restrict__ Bm,
    int m0, int n0, uint32_t* As, uint32_t* Bs, float acc[4][4][4])
{
    const int tid  = threadIdx.x;
    const int lane = tid & 31;
    const int warp = tid >> 5;
    const int wr = warp >> 2, wc = warp & 3;
    const int wm = wr * 64,  wn = wc * 32;
    const int g  = lane >> 2, tg = lane & 3;

    const int am = tid >> 1;          // A row 0..127
    const int ah = tid & 1;           // A k-half (k2 rows 0..3 / 4..7)
    const int k2b = tid >> 5;         // B k2 row 0..7
    const int bn  = (tid & 31) * 4;   // B n word offset

    const float*    Agf = (const float*)Av + (size_t)(m0 + am) * KD + ah * 8;
    const uint32_t* Agw = (const uint32_t*)Av + (size_t)(m0 + am) * (KD/2) + ah * 4;
    const float* Bg0 = Bm + (size_t)(2*k2b) * ND + n0 + bn;
    const float* Bg1 = Bg0 + ND;

    float4 ra0, ra1; uint4 rah;
    if (ABF) rah = *(const uint4*)Agw;
    else { ra0 = *(const float4*)Agf; ra1 = *(const float4*)(Agf + 4); }
    float4 rb0 = *(const float4*)Bg0;
    float4 rb1 = *(const float4*)Bg1;

    const int NIT = KD / 16;
    for (int kt = 0; kt < NIT; kt++) {
        uint32_t aw[4];
        if (ABF) { aw[0]=rah.x; aw[1]=rah.y; aw[2]=rah.z; aw[3]=rah.w; }
        else {
            aw[0] = pack_bf16(ra0.x, ra0.y);
            aw[1] = pack_bf16(ra0.z, ra0.w);
            aw[2] = pack_bf16(ra1.x, ra1.y);
            aw[3] = pack_bf16(ra1.z, ra1.w);
        }
        #pragma unroll
        for (int j = 0; j < 4; j++)
            As[(ah*4 + j)*GW + am] = aw[j];

        uint4 bw;
        bw.x = pack_bf16(rb0.x, rb1.x);
        bw.y = pack_bf16(rb0.y, rb1.y);
        bw.z = pack_bf16(rb0.z, rb1.z);
        bw.w = pack_bf16(rb0.w, rb1.w);
        *(uint4*)&Bs[k2b*GW + bn] = bw;
        __syncthreads();

        if (kt + 1 < NIT) {
            if (ABF) rah = *(const uint4*)(Agw + (kt+1)*8);
            else {
                const float* An = Agf + (kt+1)*16;
                ra0 = *(const float4*)(An);
                ra1 = *(const float4*)(An + 4);
            }
            const float* Bn0 = Bg0 + (size_t)(kt+1)*16 * ND;
            rb0 = *(const float4*)(Bn0);
            rb1 = *(const float4*)(Bn0 + ND);
        }

        uint32_t af[4][4];
        #pragma unroll
        for (int mt = 0; mt < 4; mt++) {
            const int mb = wm + mt*16 + g;
            af[mt][0] = As[tg*GW     + mb];
            af[mt][1] = As[tg*GW     + mb + 8];
            af[mt][2] = As[(tg+4)*GW + mb];
            af[mt][3] = As[(tg+4)*GW + mb + 8];
        }
        #pragma unroll
        for (int nt = 0; nt < 4; nt++) {
            const int nb = wn + nt*8 + g;
            uint32_t b0 = Bs[tg*GW     + nb];
            uint32_t b1 = Bs[(tg+4)*GW + nb];
            #pragma unroll
            for (int mt = 0; mt < 4; mt++)
                mma_bf16(acc[mt][nt], af[mt][0], af[mt][1], af[mt][2], af[mt][3], b0, b1);
        }
        __syncthreads();
    }
}

// ============================================================
// Kernel 1: QKV GEMM -> bf16 q/k/v scatter (q pre-scaled by 1/8)
// ============================================================
__global__ __launch_bounds__(256, 2) void qkv_gemm_bf(
    const float* __restrict__ A, const float* __restrict__ Wp,
    const float* __restrict__ bp)
{
    __shared__ __align__(16) uint32_t As[8*GW];
    __shared__ __align__(16) uint32_t Bs[8*GW];
    const int m0 = blockIdx.y * 128, n0 = blockIdx.x * 128;

    float acc[4][4][4];
    #pragma unroll
    for (int i = 0; i < 4; i++)
        #pragma unroll
        for (int j = 0; j < 4; j++)
            #pragma unroll
            for (int k = 0; k < 4; k++) acc[i][j][k] = 0.f;

    gemm_core<Dn, N_QKV, false>(A, Wp, m0, n0, As, Bs, acc);

    const int tid = threadIdx.x, lane = tid & 31, warp = tid >> 5;
    const int wr = warp >> 2, wc = warp & 3;
    const int g = lane >> 2, tg = lane & 3;

    const int n_warp = n0 + wc*32;
    const int which = n_warp >> 10;
    const int h     = (n_warp >> 6) & 15;
    const float scale = (which == 0) ? 0.125f : 1.f;   // fold 1/sqrt(HD) into q
    __nv_bfloat16* dstbase = (which == 0) ? g_q : (which == 1) ? g_k : g_v;
    uint32_t* dw = (uint32_t*)dstbase;

    #pragma unroll
    for (int nt = 0; nt < 4; nt++) {
        const int n = n_warp + nt*8 + 2*tg;          // even
        const int dwo = (n & 63) >> 1;               // word within head dim
        float2 bias = *(const float2*)(bp + n);
        #pragma unroll
        for (int mt = 0; mt < 4; mt++) {
            #pragma unroll
            for (int hf = 0; hf < 2; hf++) {
                const int m = m0 + wr*64 + mt*16 + g + hf*8;
                const int b = m >> 11, t = m & 2047;
                float v0 = (acc[mt][nt][hf*2+0] + bias.x) * scale;
                float v1 = (acc[mt][nt][hf*2+1] + bias.y) * scale;
                dw[((size_t)(b*Hn + h)*Tn + t)*32 + dwo] = pack_bf16(v0, v1);
            }
        }
    }
}

// ============================================================
// Kernel 2: causal attention, bf16 m16n8k16
// ============================================================
__global__ __launch_bounds__(256, 2) void attn_bf16()
{
    __shared__ __align__(16) uint32_t Qs[32*AW];   // [d2][i]
    __shared__ __align__(16) uint32_t Ks[32*AW];   // [d2][j]
    __shared__ __align__(16) uint32_t Vs[32*AW];   // [j2][d]
    __shared__ __align__(16) uint32_t Ps[32*AW];   // [j2][i]
    __shared__ float dsum[64];

    const int qb = (Tn/64 - 1) - blockIdx.x;       // heavy CTAs first
    const int h = blockIdx.y, b = blockIdx.z;
    const int tid = threadIdx.x, lane = tid & 31, warp = tid >> 5;
    const int g = lane >> 2, tg = lane & 3;
    const int band = warp >> 1, half = warp & 1;
    const int i0w = band * 16;
    const int jd0 = half * 32;

    const size_t headw = ((size_t)(b*Hn + h)) * Tn * (HDn/2);
    const uint32_t* qg = (const uint32_t*)g_q + headw;
    const uint32_t* kg = (const uint32_t*)g_k + headw;
    const uint32_t* vg = (const uint32_t*)g_v + headw;

    // stage Q: lanes span i (conflict-free STS)
    {
        const int i = tid & 63, blk = (tid >> 6) * 4;
        const uint32_t* src = qg + (size_t)(qb*64 + i)*32 + blk;
        uint4 w0 = *(const uint4*)src;
        uint4 w1 = *(const uint4*)(src + 16);
        Qs[(blk+0)*AW + i] = w0.x; Qs[(blk+1)*AW + i] = w0.y;
        Qs[(blk+2)*AW + i] = w0.z; Qs[(blk+3)*AW + i] = w0.w;
        Qs[(blk+16)*AW + i] = w1.x; Qs[(blk+17)*AW + i] = w1.y;
        Qs[(blk+18)*AW + i] = w1.z; Qs[(blk+19)*AW + i] = w1.w;
    }
    if (tid < 64) dsum[tid] = 0.f;

    float o[4][4];
    #pragma unroll
    for (int nt = 0; nt < 4; nt++)
        #pragma unroll
        for (int e = 0; e < 4; e++) o[nt][e] = 0.f;
    float rs0 = 0.f, rs1 = 0.f;

    for (int kb = 0; kb <= qb; kb++) {
        __syncthreads();   // prev PV readers done (also covers Q stage / dsum)

        // stage K
        {
            const int j = tid & 63, blk = (tid >> 6) * 4;
            const uint32_t* src = kg + (size_t)(kb*64 + j)*32 + blk;
            uint4 w0 = *(const uint4*)src;
            uint4 w1 = *(const uint4*)(src + 16);
            Ks[(blk+0)*AW + j] = w0.x; Ks[(blk+1)*AW + j] = w0.y;
            Ks[(blk+2)*AW + j] = w0.z; Ks[(blk+3)*AW + j] = w0.w;
            Ks[(blk+16)*AW + j] = w1.x; Ks[(blk+17)*AW + j] = w1.y;
            Ks[(blk+18)*AW + j] = w1.z; Ks[(blk+19)*AW + j] = w1.w;
        }
        // stage V transposed into j-pairs: Vs[j2][d] = {V[2j2][d], V[2j2+1][d]}
        {
            const int w = tid & 31;            // input word = d pair
            #pragma unroll
            for (int it = 0; it < 4; it++) {
                const int j2 = (tid >> 5) + it*8;
                uint32_t r0 = vg[(size_t)(kb*64 + 2*j2    )*32 + w];
                uint32_t r1 = vg[(size_t)(kb*64 + 2*j2 + 1)*32 + w];
                uint2 ov;
                ov.x = __byte_perm(r0, r1, 0x5410);   // d = 2w
                ov.y = __byte_perm(r0, r1, 0x7632);   // d = 2w+1
                *(uint2*)&Vs[j2*AW + 2*w] = ov;
            }
        }
        __syncthreads();

        // ---- S = Q K^T ----
        float s[4][4];
        #pragma unroll
        for (int nt = 0; nt < 4; nt++)
            #pragma unroll
            for (int e = 0; e < 4; e++) s[nt][e] = 0.f;

        #pragma unroll
        for (int kt = 0; kt < 4; kt++) {
            const int r0 = kt*8 + tg, r1 = kt*8 + tg + 4;
            uint32_t a0 = Qs[r0*AW + i0w + g];
            uint32_t a1 = Qs[r0*AW + i0w + g + 8];
            uint32_t a2 = Qs[r1*AW + i0w + g];
            uint32_t a3 = Qs[r1*AW + i0w + g + 8];
            #pragma unroll
            for (int nt = 0; nt < 4; nt++) {
                const int jc = jd0 + nt*8 + g;
                uint32_t b0 = Ks[r0*AW + jc];
                uint32_t b1 = Ks[r1*AW + jc];
                mma_bf16(s[nt], a0, a1, a2, a3, b0, b1);
            }
        }

        // ---- exp + causal mask, rowsums, pack P -> smem ----
        const bool diag = (kb == qb);
        #pragma unroll
        for (int nt = 0; nt < 4; nt++) {
            const int c = jd0 + nt*8 + 2*tg;
            float p0, p1, p2, p3;
            if (diag) {
                const int q0 = i0w + g, q1 = q0 + 8;
                p0 = (c   <= q0) ? __expf(s[nt][0]) : 0.f;
                p1 = (c+1 <= q0) ? __expf(s[nt][1]) : 0.f;
                p2 = (c   <= q1) ? __expf(s[nt][2]) : 0.f;
                p3 = (c+1 <= q1) ? __expf(s[nt][3]) : 0.f;
            } else {
                p0 = __expf(s[nt][0]); p1 = __expf(s[nt][1]);
                p2 = __expf(s[nt][2]); p3 = __expf(s[nt][3]);
            }
            rs0 += p0 + p1;
            rs1 += p2 + p3;
            const int j2 = (c >> 1);
            Ps[j2*AW + i0w + g    ] = pack_bf16(p0, p1);
            Ps[j2*AW + i0w + g + 8] = pack_bf16(p2, p3);
        }
        __syncthreads();   // full P tile visible

        // ---- O += P V ----
        #pragma unroll
        for (int kt = 0; kt < 4; kt++) {
            const int r0 = kt*8 + tg, r1 = kt*8 + tg + 4;
            uint32_t a0 = Ps[r0*AW + i0w + g];
            uint32_t a1 = Ps[r0*AW + i0w + g + 8];
            uint32_t a2 = Ps[r1*AW + i0w + g];
            uint32_t a3 = Ps[r1*AW + i0w + g + 8];
            #pragma unroll
            for (int nt = 0; nt < 4; nt++) {
                const int dc = jd0 + nt*8 + g;
                uint32_t b0 = Vs[r0*AW + dc];
                uint32_t b1 = Vs[r1*AW + dc];
                mma_bf16(o[nt], a0, a1, a2, a3, b0, b1);
            }
        }
    }

    // row-sum combine
    rs0 += __shfl_xor_sync(0xffffffffu, rs0, 1);
    rs0 += __shfl_xor_sync(0xffffffffu, rs0, 2);
    rs1 += __shfl_xor_sync(0xffffffffu, rs1, 1);
    rs1 += __shfl_xor_sync(0xffffffffu, rs1, 2);
    if (tg == 0) {
        atomicAdd(&dsum[i0w + g],     rs0);
        atomicAdd(&dsum[i0w + g + 8], rs1);
    }
    __syncthreads();
    const float inv0 = 1.f / (dsum[i0w + g]     + 1e-9f);
    const float inv1 = 1.f / (dsum[i0w + g + 8] + 1e-9f);

    uint32_t* yb = (uint32_t*)g_y + ((size_t)(b*Tn + qb*64))*512 + h*32;
    #pragma unroll
    for (int nt = 0; nt < 4; nt++) {
        const int c = jd0 + nt*8 + 2*tg;
        yb[(size_t)(i0w + g    )*512 + (c >> 1)] = pack_bf16(o[nt][0]*inv0, o[nt][1]*inv0);
        yb[(size_t)(i0w + g + 8)*512 + (c >> 1)] = pack_bf16(o[nt][2]*inv1, o[nt][3]*inv1);
    }
}

// ============================================================
// Kernel 3: out projection (bf16 A from g_y) + residual -> g_z
// ============================================================
__global__ __launch_bounds__(256, 2) void outproj_gemm_bf(
    const float* __restrict__ X, const float* __restrict__ Wo,
    const float* __restrict__ bo)
{
    __shared__ __align__(16) uint32_t As[8*GW];
    __shared__ __align__(16) uint32_t Bs[8*GW];
    const int m0 = blockIdx.y * 128, n0 = blockIdx.x * 128;

    float acc[4][4][4];
    #pragma unroll
    for (int i = 0; i < 4; i++)
        #pragma unroll
        for (int j = 0; j < 4; j++)
            #pragma unroll
            for (int k = 0; k < 4; k++) acc[i][j][k] = 0.f;

    gemm_core<Dn, Dn, true>(g_y, Wo, m0, n0, As, Bs, acc);

    const int tid = threadIdx.x, lane = tid & 31, warp = tid >> 5;
    const int wr = warp >> 2, wc = warp & 3;
    const int g = lane >> 2, tg = lane & 3;

    #pragma unroll
    for (int nt = 0; nt < 4; nt++) {
        const int n = n0 + wc*32 + nt*8 + 2*tg;
        float2 bias = *(const float2*)(bo + n);
        #pragma unroll
        for (int mt = 0; mt < 4; mt++) {
            #pragma unroll
            for (int hf = 0; hf < 2; hf++) {
                const int m = m0 + wr*64 + mt*16 + g + hf*8;
                float2 xr = *(const float2*)(X + (size_t)m * Dn + n);
                float2 v;
                v.x = acc[mt][nt][hf*2+0] + bias.x + xr.x;
                v.y = acc[mt][nt][hf*2+1] + bias.y + xr.y;
                *(float2*)(g_z + (size_t)m * Dn + n) = v;
            }
        }
    }
}

// ============================================================
// Kernel 4: LayerNorm over last dim (1024), one CTA per row
// ============================================================
__global__ __launch_bounds__(256) void ln_kernel(
    const float* __restrict__ gamma, const float* __restrict__ beta,
    float* __restrict__ out)
{
    int row = blockIdx.x;
    int tid = threadIdx.x;
    const float* z = g_z + (size_t)row * Dn + tid*4;
    float4 v = *(const float4*)z;
    float s  = v.x + v.y + v.z + v.w;
    float ss = v.x*v.x + v.y*v.y + v.z*v.z + v.w*v.w;

    #pragma unroll
    for (int off = 16; off; off >>= 1) {
        s  += __shfl_xor_sync(0xffffffffu, s,  off);
        ss += __shfl_xor_sync(0xffffffffu, ss, off);
    }

    __shared__ float rs[8], rss[8];
    __shared__ float smu, srstd;
    int wid = tid >> 5, lane = tid & 31;
    if (lane == 0) { rs[wid] = s; rss[wid] = ss; }
    __syncthreads();
    if (tid == 0) {
        float S = 0.f, SS = 0.f;
        #pragma unroll
        for (int w = 0; w < 8; w++) { S += rs[w]; SS += rss[w]; }
        float mu  = S * (1.f / Dn);
        float var = SS * (1.f / Dn) - mu * mu;
        smu = mu;
        srstd = rsqrtf(var + 1e-5f);
    }
    __syncthreads();
    float mu = smu, rstd = srstd;

    float4 g4 = *(const float4*)(gamma + tid*4);
    float4 b4 = *(const float4*)(beta  + tid*4);
    float4 o;
    o.x = (v.x - mu)*rstd*g4.x + b4.x;
    o.y = (v.y - mu)*rstd*g4.y + b4.y;
    o.z = (v.z - mu)*rstd*g4.z + b4.z;
    o.w = (v.w - mu)*rstd*g4.w + b4.w;
    *(float4*)(out + (size_t)row * Dn + tid*4) = o;
}

// ============================================================
extern "C" void kernel_launch(void* const* d_in, const int* in_sizes, int n_in,
                              void* d_out, int out_size)
{
    (void)in_sizes; (void)n_in; (void)out_size;
    const float* x    = (const float*)d_in[0];
    // d_in[1] = attn_mask: deterministic causal, not needed
    const float* Wp   = (const float*)d_in[2];
    const float* bp   = (const float*)d_in[3];
    const float* Wo   = (const float*)d_in[4];
    const float* bo   = (const float*)d_in[5];
    const float* gam  = (const float*)d_in[6];
    const float* bet  = (const float*)d_in[7];
    float* out = (float*)d_out;

    qkv_gemm_bf<<<dim3(N_QKV/128, M_TOT/128), 256>>>(x, Wp, bp);

    attn_bf16<<<dim3(Tn/64, Hn, Bn), 256>>>();

    outproj_gemm_bf<<<dim3(Dn/128, M_TOT/128), 256>>>(x, Wo, bo);

    ln_kernel<<<M_TOT, 256>>>(gam, bet, out);
}

// round 6
// speedup vs baseline: 4.8833x; 1.1381x over previous
#include <cuda_runtime.h>
#include <cuda_bf16.h>
#include <math.h>
#include <stdint.h>

#define Bn  2
#define Tn  2048
#define Dn  1024
#define Hn  16
#define HDn 64
#define M_TOT 4096
#define N_QKV 3072
#define AW  72     // attention smem word stride (72 % 32 == 8)

// -------- scratch (device globals: allocation-free) --------
__device__ __nv_bfloat16 g_q[(size_t)Bn*Hn*Tn*HDn];
__device__ __nv_bfloat16 g_k[(size_t)Bn*Hn*Tn*HDn];
__device__ __nv_bfloat16 g_v[(size_t)Bn*Hn*Tn*HDn];
__device__ float g_z[(size_t)M_TOT*Dn];
// k2-major packed bf16x2 images: img[k/2][m] (A-side) / img[k/2][n] (B-side)
__device__ uint32_t g_ximg[(size_t)(Dn/2)*M_TOT];
__device__ uint32_t g_yimg[(size_t)(Dn/2)*M_TOT];
__device__ uint32_t g_wpimg[(size_t)(Dn/2)*N_QKV];
__device__ uint32_t g_woimg[(size_t)(Dn/2)*Dn];

// ---------------- helpers ----------------
__device__ __forceinline__ uint32_t pack_bf16(float lo, float hi) {
    uint32_t r;
    asm("cvt.rn.bf16x2.f32 %0, %1, %2;" : "=r"(r) : "f"(hi), "f"(lo));
    return r;
}

__device__ __forceinline__ void mma_bf16(float d[4],
                                         uint32_t a0, uint32_t a1, uint32_t a2, uint32_t a3,
                                         uint32_t b0, uint32_t b1) {
    asm volatile(
        "mma.sync.aligned.m16n8k16.row.col.f32.bf16.bf16.f32 "
        "{%0,%1,%2,%3}, {%4,%5,%6,%7}, {%8,%9}, {%0,%1,%2,%3};\n"
        : "+f"(d[0]), "+f"(d[1]), "+f"(d[2]), "+f"(d[3])
        : "r"(a0), "r"(a1), "r"(a2), "r"(a3), "r"(b0), "r"(b1));
}

__device__ __forceinline__ uint32_t smem_u32(const void* p) {
    uint32_t a;
    asm("{ .reg .u64 t; cvta.to.shared.u64 t, %1; cvt.u32.u64 %0, t; }"
        : "=r"(a) : "l"(p));
    return a;
}

__device__ __forceinline__ void cp16(uint32_t dst, const void* src) {
    asm volatile("cp.async.cg.shared.global [%0], [%1], 16;"
                 :: "r"(dst), "l"(src) : "memory");
}
#define CP_COMMIT() asm volatile("cp.async.commit_group;" ::: "memory")
#define CP_WAIT1()  asm volatile("cp.async.wait_group 1;" ::: "memory")
#define CP_WAIT0()  asm volatile("cp.async.wait_group 0;" ::: "memory")

// ============================================================
// Prep kernels: build k2-major packed images
// ============================================================
// x [M,1024] fp32 -> g_ximg[k2][m]
__global__ __launch_bounds__(256) void pack_x_img(const float* __restrict__ x)
{
    __shared__ float tile[64][65];
    const int k0 = blockIdx.x * 64, m0 = blockIdx.y * 64;
    const int tid = threadIdx.x;
    #pragma unroll
    for (int p = 0; p < 4; p++) {
        int idx = tid + p * 256;
        int r = idx >> 4;
        int c4 = (idx & 15) * 4;
        float4 v = *(const float4*)(x + (size_t)(m0 + r) * Dn + k0 + c4);
        tile[r][c4] = v.x; tile[r][c4+1] = v.y;
        tile[r][c4+2] = v.z; tile[r][c4+3] = v.w;
    }
    __syncthreads();
    const int ml = tid & 63, kg = tid >> 6;
    #pragma unroll
    for (int j = 0; j < 8; j++) {
        int k2l = kg * 8 + j;
        uint32_t w = pack_bf16(tile[ml][2*k2l], tile[ml][2*k2l+1]);
        g_ximg[(size_t)(k0/2 + k2l) * M_TOT + m0 + ml] = w;
    }
}

// W [1024][N] fp32 -> img[k2][n]  (no transpose needed; gather 2 rows)
__global__ __launch_bounds__(256) void pack_w_img(
    const float* __restrict__ W, int N, int isout)
{
    const int n = blockIdx.x * 256 + threadIdx.x;
    const int k2 = blockIdx.y;
    uint32_t w = pack_bf16(W[(size_t)(2*k2) * N + n], W[(size_t)(2*k2+1) * N + n]);
    (isout ? g_woimg : g_wpimg)[(size_t)k2 * N + n] = w;
}

// ============================================================
// bf16 HMMA GEMM: CTA 128x256, 8 warps of 64x64, BK=16,
// 3-stage cp.async pipeline, one __syncthreads per k-step.
// A = img[k2][M_TOT], B = img[k2][ND]. acc[4][8][4] fp32.
// ============================================================
template <int ND, bool IS_QKV>
__global__ __launch_bounds__(256, 1) void gemm_mma(
    const float* __restrict__ bias, const float* __restrict__ Xres)
{
    // stage = A(8 rows x 136w) + B(8 rows x 264w) = 3200 words
    __shared__ __align__(16) uint32_t sm[3 * 3200];

    const int tid = threadIdx.x, lane = tid & 31, warp = tid >> 5;
    const int g = lane >> 2, tg = lane & 3;
    const int wr = warp >> 2, wc = warp & 3;
    const int m0 = blockIdx.y * 128, n0 = blockIdx.x * 256;

    const uint32_t* Aimg = IS_QKV ? g_ximg : g_yimg;
    const uint32_t* Bimg = IS_QKV ? g_wpimg : g_woimg;

    float acc[4][8][4];
    #pragma unroll
    for (int i = 0; i < 4; i++)
        #pragma unroll
        for (int j = 0; j < 8; j++)
            #pragma unroll
            for (int e = 0; e < 4; e++) acc[i][j][e] = 0.f;

    // --- staging (one A cp + two B cps per thread per chunk) ---
    const int ar = tid >> 5, aseg = tid & 31;
    auto stagef = [&](int kt) {
        uint32_t* As = sm + (kt % 3) * 3200;
        uint32_t* Bs = As + 1088;
        cp16(smem_u32(As + ar*136 + aseg*4),
             Aimg + (size_t)(kt*8 + ar) * M_TOT + m0 + aseg*4);
        #pragma unroll
        for (int p = 0; p < 2; p++) {
            int idx = tid + p * 256;
            int r = idx >> 6, seg = idx & 63;
            cp16(smem_u32(Bs + r*264 + seg*4),
                 Bimg + (size_t)(kt*8 + r) * ND + n0 + seg*4);
        }
        CP_COMMIT();
    };

    stagef(0);
    stagef(1);

    #pragma unroll 1
    for (int kt = 0; kt < 64; kt++) {
        if (kt + 2 < 64) { CP_WAIT1(); } else { CP_WAIT0(); }
        __syncthreads();
        if (kt + 2 < 64) stagef(kt + 2);

        const uint32_t* As = sm + (kt % 3) * 3200;
        const uint32_t* Bs = As + 1088;

        uint32_t af[4][4];
        #pragma unroll
        for (int mt = 0; mt < 4; mt++) {
            const int mb = wr*64 + mt*16 + g;
            af[mt][0] = As[tg*136 + mb];
            af[mt][1] = As[tg*136 + mb + 8];
            af[mt][2] = As[(tg+4)*136 + mb];
            af[mt][3] = As[(tg+4)*136 + mb + 8];
        }
        #pragma unroll
        for (int nt = 0; nt < 8; nt++) {
            const int nb = wc*64 + nt*8 + g;
            uint32_t b0 = Bs[tg*264 + nb];
            uint32_t b1 = Bs[(tg+4)*264 + nb];
            #pragma unroll
            for (int mt = 0; mt < 4; mt++)
                mma_bf16(acc[mt][nt], af[mt][0], af[mt][1], af[mt][2], af[mt][3], b0, b1);
        }
    }

    // ---- epilogue ----
    const int ncb = n0 + wc * 64;         // 64-aligned -> single (which,h)
    float2 bi[8];
    #pragma unroll
    for (int nt = 0; nt < 8; nt++)
        bi[nt] = *(const float2*)(bias + ncb + nt*8 + 2*tg);

    if (IS_QKV) {
        const int which = ncb >> 10;
        const int h = (ncb >> 6) & 15;
        const float scale = (which == 0) ? 0.125f : 1.f;   // fold 1/sqrt(HD) into q
        uint32_t* base = (which == 0) ? (uint32_t*)g_q :
                         (which == 1) ? (uint32_t*)g_k : (uint32_t*)g_v;
        #pragma unroll
        for (int mt = 0; mt < 4; mt++) {
            #pragma unroll
            for (int hf = 0; hf < 2; hf++) {
                const int m = m0 + wr*64 + mt*16 + g + hf*8;
                const int b = m >> 11, t = m & 2047;
                uint32_t* dst = base + ((size_t)(b*Hn + h)*Tn + t) * 32;
                #pragma unroll
                for (int nt = 0; nt < 8; nt++)
                    dst[nt*4 + tg] = pack_bf16(
                        (acc[mt][nt][hf*2+0] + bi[nt].x) * scale,
                        (acc[mt][nt][hf*2+1] + bi[nt].y) * scale);
            }
        }
    } else {
        #pragma unroll
        for (int mt = 0; mt < 4; mt++) {
            #pragma unroll
            for (int hf = 0; hf < 2; hf++) {
                const int m = m0 + wr*64 + mt*16 + g + hf*8;
                const float* xr = Xres + (size_t)m * Dn + ncb;
                float* zr = g_z + (size_t)m * Dn + ncb;
                #pragma unroll
                for (int nt = 0; nt < 8; nt++) {
                    const int off = nt*8 + 2*tg;
                    float2 xv = *(const float2*)(xr + off);
                    float2 o;
                    o.x = acc[mt][nt][hf*2+0] + bi[nt].x + xv.x;
                    o.y = acc[mt][nt][hf*2+1] + bi[nt].y + xv.y;
                    *(float2*)(zr + off) = o;
                }
            }
        }
    }
}

// ============================================================
// Causal attention, bf16 m16n8k16 (R4 core; epilogue -> g_yimg)
// ============================================================
__global__ __launch_bounds__(256, 2) void attn_bf16()
{
    __shared__ __align__(16) uint32_t Qs[32*AW];   // [d2][i]
    __shared__ __align__(16) uint32_t Ks[32*AW];   // [d2][j]
    __shared__ __align__(16) uint32_t Vs[32*AW];   // [j2][d]
    __shared__ __align__(16) uint32_t Ps[32*AW];   // [j2][i]
    __shared__ float dsum[64];

    const int qb = (Tn/64 - 1) - blockIdx.x;       // heavy CTAs first
    const int h = blockIdx.y, b = blockIdx.z;
    const int tid = threadIdx.x, lane = tid & 31, warp = tid >> 5;
    const int g = lane >> 2, tg = lane & 3;
    const int band = warp >> 1, half = warp & 1;
    const int i0w = band * 16;
    const int jd0 = half * 32;

    const size_t headw = ((size_t)(b*Hn + h)) * Tn * (HDn/2);
    const uint32_t* qg = (const uint32_t*)g_q + headw;
    const uint32_t* kg = (const uint32_t*)g_k + headw;
    const uint32_t* vg = (const uint32_t*)g_v + headw;

    {
        const int i = tid & 63, blk = (tid >> 6) * 4;
        const uint32_t* src = qg + (size_t)(qb*64 + i)*32 + blk;
        uint4 w0 = *(const uint4*)src;
        uint4 w1 = *(const uint4*)(src + 16);
        Qs[(blk+0)*AW + i] = w0.x; Qs[(blk+1)*AW + i] = w0.y;
        Qs[(blk+2)*AW + i] = w0.z; Qs[(blk+3)*AW + i] = w0.w;
        Qs[(blk+16)*AW + i] = w1.x; Qs[(blk+17)*AW + i] = w1.y;
        Qs[(blk+18)*AW + i] = w1.z; Qs[(blk+19)*AW + i] = w1.w;
    }
    if (tid < 64) dsum[tid] = 0.f;

    float o[4][4];
    #pragma unroll
    for (int nt = 0; nt < 4; nt++)
        #pragma unroll
        for (int e = 0; e < 4; e++) o[nt][e] = 0.f;
    float rs0 = 0.f, rs1 = 0.f;

    for (int kb = 0; kb <= qb; kb++) {
        __syncthreads();

        {
            const int j = tid & 63, blk = (tid >> 6) * 4;
            const uint32_t* src = kg + (size_t)(kb*64 + j)*32 + blk;
            uint4 w0 = *(const uint4*)src;
            uint4 w1 = *(const uint4*)(src + 16);
            Ks[(blk+0)*AW + j] = w0.x; Ks[(blk+1)*AW + j] = w0.y;
            Ks[(blk+2)*AW + j] = w0.z; Ks[(blk+3)*AW + j] = w0.w;
            Ks[(blk+16)*AW + j] = w1.x; Ks[(blk+17)*AW + j] = w1.y;
            Ks[(blk+18)*AW + j] = w1.z; Ks[(blk+19)*AW + j] = w1.w;
        }
        {
            const int w = tid & 31;
            #pragma unroll
            for (int it = 0; it < 4; it++) {
                const int j2 = (tid >> 5) + it*8;
                uint32_t r0 = vg[(size_t)(kb*64 + 2*j2    )*32 + w];
                uint32_t r1 = vg[(size_t)(kb*64 + 2*j2 + 1)*32 + w];
                uint2 ov;
                ov.x = __byte_perm(r0, r1, 0x5410);
                ov.y = __byte_perm(r0, r1, 0x7632);
                *(uint2*)&Vs[j2*AW + 2*w] = ov;
            }
        }
        __syncthreads();

        float s[4][4];
        #pragma unroll
        for (int nt = 0; nt < 4; nt++)
            #pragma unroll
            for (int e = 0; e < 4; e++) s[nt][e] = 0.f;

        #pragma unroll
        for (int kt = 0; kt < 4; kt++) {
            const int r0 = kt*8 + tg, r1 = kt*8 + tg + 4;
            uint32_t a0 = Qs[r0*AW + i0w + g];
            uint32_t a1 = Qs[r0*AW + i0w + g + 8];
            uint32_t a2 = Qs[r1*AW + i0w + g];
            uint32_t a3 = Qs[r1*AW + i0w + g + 8];
            #pragma unroll
            for (int nt = 0; nt < 4; nt++) {
                const int jc = jd0 + nt*8 + g;
                uint32_t b0 = Ks[r0*AW + jc];
                uint32_t b1 = Ks[r1*AW + jc];
                mma_bf16(s[nt], a0, a1, a2, a3, b0, b1);
            }
        }

        const bool diag = (kb == qb);
        #pragma unroll
        for (int nt = 0; nt < 4; nt++) {
            const int c = jd0 + nt*8 + 2*tg;
            float p0, p1, p2, p3;
            if (diag) {
                const int q0 = i0w + g, q1 = q0 + 8;
                p0 = (c   <= q0) ? __expf(s[nt][0]) : 0.f;
                p1 = (c+1 <= q0) ? __expf(s[nt][1]) : 0.f;
                p2 = (c   <= q1) ? __expf(s[nt][2]) : 0.f;
                p3 = (c+1 <= q1) ? __expf(s[nt][3]) : 0.f;
            } else {
                p0 = __expf(s[nt][0]); p1 = __expf(s[nt][1]);
                p2 = __expf(s[nt][2]); p3 = __expf(s[nt][3]);
            }
            rs0 += p0 + p1;
            rs1 += p2 + p3;
            const int j2 = (c >> 1);
            Ps[j2*AW + i0w + g    ] = pack_bf16(p0, p1);
            Ps[j2*AW + i0w + g + 8] = pack_bf16(p2, p3);
        }
        __syncthreads();

        #pragma unroll
        for (int kt = 0; kt < 4; kt++) {
            const int r0 = kt*8 + tg, r1 = kt*8 + tg + 4;
            uint32_t a0 = Ps[r0*AW + i0w + g];
            uint32_t a1 = Ps[r0*AW + i0w + g + 8];
            uint32_t a2 = Ps[r1*AW + i0w + g];
            uint32_t a3 = Ps[r1*AW + i0w + g + 8];
            #pragma unroll
            for (int nt = 0; nt < 4; nt++) {
                const int dc = jd0 + nt*8 + g;
                uint32_t b0 = Vs[r0*AW + dc];
                uint32_t b1 = Vs[r1*AW + dc];
                mma_bf16(o[nt], a0, a1, a2, a3, b0, b1);
            }
        }
    }

    rs0 += __shfl_xor_sync(0xffffffffu, rs0, 1);
    rs0 += __shfl_xor_sync(0xffffffffu, rs0, 2);
    rs1 += __shfl_xor_sync(0xffffffffu, rs1, 1);
    rs1 += __shfl_xor_sync(0xffffffffu, rs1, 2);
    if (tg == 0) {
        atomicAdd(&dsum[i0w + g],     rs0);
        atomicAdd(&dsum[i0w + g + 8], rs1);
    }
    __syncthreads();
    const float inv0 = 1.f / (dsum[i0w + g]     + 1e-9f);
    const float inv1 = 1.f / (dsum[i0w + g + 8] + 1e-9f);

    // write k2-major image for the proj GEMM: g_yimg[(h*32+c2)][m]
    const int mrow = b*Tn + qb*64;
    #pragma unroll
    for (int nt = 0; nt < 4; nt++) {
        const int c2 = (jd0 >> 1) + nt*4 + tg;
        uint32_t* yw = g_yimg + (size_t)(h*32 + c2) * M_TOT + mrow;
        yw[i0w + g    ] = pack_bf16(o[nt][0]*inv0, o[nt][1]*inv0);
        yw[i0w + g + 8] = pack_bf16(o[nt][2]*inv1, o[nt][3]*inv1);
    }
}

// ============================================================
// LayerNorm (unchanged)
// ============================================================
__global__ __launch_bounds__(256) void ln_kernel(
    const float* __restrict__ gamma, const float* __restrict__ beta,
    float* __restrict__ out)
{
    int row = blockIdx.x;
    int tid = threadIdx.x;
    const float* z = g_z + (size_t)row * Dn + tid*4;
    float4 v = *(const float4*)z;
    float s  = v.x + v.y + v.z + v.w;
    float ss = v.x*v.x + v.y*v.y + v.z*v.z + v.w*v.w;

    #pragma unroll
    for (int off = 16; off; off >>= 1) {
        s  += __shfl_xor_sync(0xffffffffu, s,  off);
        ss += __shfl_xor_sync(0xffffffffu, ss, off);
    }

    __shared__ float rs[8], rss[8];
    __shared__ float smu, srstd;
    int wid = tid >> 5, lane = tid & 31;
    if (lane == 0) { rs[wid] = s; rss[wid] = ss; }
    __syncthreads();
    if (tid == 0) {
        float S = 0.f, SS = 0.f;
        #pragma unroll
        for (int w = 0; w < 8; w++) { S += rs[w]; SS += rss[w]; }
        float mu  = S * (1.f / Dn);
        float var = SS * (1.f / Dn) - mu * mu;
        smu = mu;
        srstd = rsqrtf(var + 1e-5f);
    }
    __syncthreads();
    float mu = smu, rstd = srstd;

    float4 g4 = *(const float4*)(gamma + tid*4);
    float4 b4 = *(const float4*)(beta  + tid*4);
    float4 o;
    o.x = (v.x - mu)*rstd*g4.x + b4.x;
    o.y = (v.y - mu)*rstd*g4.y + b4.y;
    o.z = (v.z - mu)*rstd*g4.z + b4.z;
    o.w = (v.w - mu)*rstd*g4.w + b4.w;
    *(float4*)(out + (size_t)row * Dn + tid*4) = o;
}

// ============================================================
extern "C" void kernel_launch(void* const* d_in, const int* in_sizes, int n_in,
                              void* d_out, int out_size)
{
    (void)in_sizes; (void)n_in; (void)out_size;
    const float* x    = (const float*)d_in[0];
    // d_in[1] = attn_mask: deterministic causal, not needed
    const float* Wp   = (const float*)d_in[2];
    const float* bp   = (const float*)d_in[3];
    const float* Wo   = (const float*)d_in[4];
    const float* bo   = (const float*)d_in[5];
    const float* gam  = (const float*)d_in[6];
    const float* bet  = (const float*)d_in[7];
    float* out = (float*)d_out;

    pack_x_img<<<dim3(Dn/64, M_TOT/64), 256>>>(x);
    pack_w_img<<<dim3(N_QKV/256, Dn/2), 256>>>(Wp, N_QKV, 0);
    pack_w_img<<<dim3(Dn/256,   Dn/2), 256>>>(Wo, Dn, 1);

    gemm_mma<N_QKV, true><<<dim3(N_QKV/256, M_TOT/128), 256>>>(bp, nullptr);

    attn_bf16<<<dim3(Tn/64, Hn, Bn), 256>>>();

    gemm_mma<Dn, false><<<dim3(Dn/256, M_TOT/128), 256>>>(bo, x);

    ln_kernel<<<M_TOT, 256>>>(gam, bet, out);
}